// round 3
// baseline (speedup 1.0000x reference)
#include <cuda_runtime.h>
#include <cuda_bf16.h>
#include <cstdint>
#include <cfloat>

#define JAX_PARTITIONABLE 1   // flip to 0 if rel_err shows sampling mismatch

#define NB      4096
#define NDIM    128
#define BM      32
#define BN      128
#define NTHREADS 256

// ---------------- device scratch (static, no allocation) --------------------
__device__ float g_embT[NDIM * NB];
__device__ float g_sqnorm[NB];
__device__ int   g_negidx[NB];
__device__ int   g_posidx[NB];
__device__ float g_loss[NB];
__device__ float g_cnt[NB];

// ---------------- threefry2x32 ----------------------------------------------
__host__ __device__ __forceinline__ void tf2x32(uint32_t k0, uint32_t k1,
                                                uint32_t c0, uint32_t c1,
                                                uint32_t& o0, uint32_t& o1) {
    const uint32_t ks2 = k0 ^ k1 ^ 0x1BD11BDAu;
    uint32_t x0 = c0 + k0;
    uint32_t x1 = c1 + k1;
#define TFR(r) { x0 += x1; x1 = (x1 << r) | (x1 >> (32 - r)); x1 ^= x0; }
    TFR(13) TFR(15) TFR(26) TFR(6)   x0 += k1;  x1 += ks2 + 1u;
    TFR(17) TFR(29) TFR(16) TFR(24)  x0 += ks2; x1 += k0  + 2u;
    TFR(13) TFR(15) TFR(26) TFR(6)   x0 += k0;  x1 += k1  + 3u;
    TFR(17) TFR(29) TFR(16) TFR(24)  x0 += k1;  x1 += ks2 + 4u;
    TFR(13) TFR(15) TFR(26) TFR(6)   x0 += ks2; x1 += k0  + 5u;
#undef TFR
    o0 = x0; o1 = x1;
}

// random 32 bits for flat index n (n < 2^24 so counter-hi = 0)
__device__ __forceinline__ uint32_t jax_bits32(uint32_t k0, uint32_t k1, uint32_t n) {
    uint32_t o0, o1;
#if JAX_PARTITIONABLE
    tf2x32(k0, k1, 0u, n, o0, o1);
    return o0 ^ o1;
#else
    const uint32_t H = (uint32_t)(NB) * (uint32_t)(NB) / 2u;
    if (n < H) { tf2x32(k0, k1, n, n + H, o0, o1); return o0; }
    else       { tf2x32(k0, k1, n - H, n, o0, o1); return o1; }
#endif
}

__device__ __forceinline__ float jax_gumbel(uint32_t bits) {
    float f = __uint_as_float((bits >> 9) | 0x3f800000u) - 1.0f;
    float u = fmaxf(f, 1.17549435e-38f);
    float nl = -logf(u);               // accurate: u->1 tail matters
    return -__logf(nl);
}

// pack (value, idx) so max() == argmax, first-index tie-break
__device__ __forceinline__ unsigned long long pack_vi(float v, int idx) {
    uint32_t s = __float_as_uint(v);
    s = (s & 0x80000000u) ? ~s : (s | 0x80000000u);
    return ((unsigned long long)s << 32) | (uint32_t)(0xFFFFFFFFu - (uint32_t)idx);
}

// ---------------- prep kernels ----------------------------------------------
__global__ void transpose_k(const float* __restrict__ emb) {
    __shared__ float t[32][33];
    int rb = blockIdx.x * 32, kb = blockIdx.y * 32;
    int tx = threadIdx.x, ty = threadIdx.y;
#pragma unroll
    for (int j = 0; j < 4; j++)
        t[ty + j * 8][tx] = emb[(rb + ty + j * 8) * NDIM + kb + tx];
    __syncthreads();
#pragma unroll
    for (int j = 0; j < 4; j++)
        g_embT[(kb + ty + j * 8) * NB + rb + tx] = t[tx][ty + j * 8];
}

__global__ void norm_k(const float* __restrict__ emb) {
    int w = (blockIdx.x * blockDim.x + threadIdx.x) >> 5;
    int lane = threadIdx.x & 31;
    if (w >= NB) return;
    float4 v = *(const float4*)(emb + w * NDIM + lane * 4);
    float s = v.x * v.x + v.y * v.y + v.z * v.z + v.w * v.w;
#pragma unroll
    for (int o = 16; o; o >>= 1) s += __shfl_xor_sync(0xFFFFFFFFu, s, o);
    if (lane == 0) g_sqnorm[w] = s;
}

// ---------------- main: Gram tile + logits + gumbel + row-argmax ------------
__global__ void __launch_bounds__(NTHREADS, 1)
neg_sample_k(const int* __restrict__ labels, uint32_t kn0, uint32_t kn1) {
    extern __shared__ char sm[];
    float* A_s = (float*)sm;                       // [128][32]  k-major
    float* B_s = A_s + NDIM * BM;                  // [128][128] k-major
    int*   labc = (int*)(B_s + NDIM * BN);         // [128]
    float* sqc  = (float*)(labc + BN);             // [128]
    unsigned long long* red = (unsigned long long*)(sqc + BN);   // [32]

    const int tid = threadIdx.x;
    const int tr = tid >> 5;
    const int tc = tid & 31;
    const int row0 = blockIdx.x * BM;

    float sqr[4]; int labr[4];
#pragma unroll
    for (int m = 0; m < 4; m++) {
        sqr[m]  = g_sqnorm[row0 + tr * 4 + m];
        labr[m] = labels[row0 + tr * 4 + m];
    }
    unsigned long long best[4] = {0ull, 0ull, 0ull, 0ull};

    for (int idx = tid; idx < NDIM * BM; idx += NTHREADS) {
        int k = idx >> 5, q = idx & 31;
        A_s[k * BM + q] = g_embT[k * NB + row0 + q];
    }

    for (int ct = 0; ct < NB; ct += BN) {
        __syncthreads();
        for (int idx = tid; idx < NDIM * BN / 4; idx += NTHREADS) {
            int k = idx >> 5, q = idx & 31;
            *(float4*)&B_s[k * BN + q * 4] =
                *(const float4*)&g_embT[k * NB + ct + q * 4];
        }
        if (tid < BN) { labc[tid] = labels[ct + tid]; sqc[tid] = g_sqnorm[ct + tid]; }
        __syncthreads();

        float acc[4][4];
#pragma unroll
        for (int m = 0; m < 4; m++)
#pragma unroll
            for (int c = 0; c < 4; c++) acc[m][c] = 0.f;

#pragma unroll 8
        for (int k = 0; k < NDIM; k++) {
            float4 a = *(const float4*)(A_s + k * BM + (tr << 2));
            float4 b = *(const float4*)(B_s + k * BN + (tc << 2));
            acc[0][0] = fmaf(a.x, b.x, acc[0][0]);
            acc[0][1] = fmaf(a.x, b.y, acc[0][1]);
            acc[0][2] = fmaf(a.x, b.z, acc[0][2]);
            acc[0][3] = fmaf(a.x, b.w, acc[0][3]);
            acc[1][0] = fmaf(a.y, b.x, acc[1][0]);
            acc[1][1] = fmaf(a.y, b.y, acc[1][1]);
            acc[1][2] = fmaf(a.y, b.z, acc[1][2]);
            acc[1][3] = fmaf(a.y, b.w, acc[1][3]);
            acc[2][0] = fmaf(a.z, b.x, acc[2][0]);
            acc[2][1] = fmaf(a.z, b.y, acc[2][1]);
            acc[2][2] = fmaf(a.z, b.z, acc[2][2]);
            acc[2][3] = fmaf(a.z, b.w, acc[2][3]);
            acc[3][0] = fmaf(a.w, b.x, acc[3][0]);
            acc[3][1] = fmaf(a.w, b.y, acc[3][1]);
            acc[3][2] = fmaf(a.w, b.z, acc[3][2]);
            acc[3][3] = fmaf(a.w, b.w, acc[3][3]);
        }

#pragma unroll
        for (int cc = 0; cc < 4; cc++) {
            const int jl = tc * 4 + cc;
            const int j  = ct + jl;
            const int labj = labc[jl];
            const float sqj = sqc[jl];
#pragma unroll
            for (int m = 0; m < 4; m++) {
                if (labr[m] == labj) continue;      // same-label -> -inf logit
                const int i = row0 + tr * 4 + m;
                float d2 = (sqr[m] + sqj) - 2.0f * acc[m][cc];
                d2 = fmaxf(d2, 0.25f);              // == clip d at 0.5
                float d = sqrtf(d2);
                float lq = -126.0f * __logf(d)
                           - 62.5f * log1pf((-0.25f * d) * d);
                uint32_t bits = jax_bits32(kn0, kn1, (uint32_t)(i * NB + j));
                float v = lq + jax_gumbel(bits);
                unsigned long long p = pack_vi(v, j);
                if (p > best[m]) best[m] = p;
            }
        }
    }

    __syncthreads();
    if (tid < BM) red[tid] = 0ull;
    __syncthreads();
#pragma unroll
    for (int m = 0; m < 4; m++)
        atomicMax(&red[tr * 4 + m], best[m]);
    __syncthreads();
    if (tid < BM)
        g_negidx[row0 + tid] = (int)(0xFFFFFFFFu - (uint32_t)red[tid]);
}

// ---------------- positives: uniform gumbel argmax over same-label ----------
__global__ void pos_sample_k(const int* __restrict__ labels,
                             uint32_t kp0, uint32_t kp1) {
    __shared__ int lab[NB];
    int t = threadIdx.x;
    for (int i = t; i < NB; i += 128) lab[i] = labels[i];
    __syncthreads();
    int i = blockIdx.x * 128 + t;
    int li = lab[i];
    unsigned long long best = 0ull;
    for (int j = 0; j < NB; j++) {
        if (lab[j] == li && j != i) {
            uint32_t bits = jax_bits32(kp0, kp1, (uint32_t)(i * NB + j));
            unsigned long long p = pack_vi(jax_gumbel(bits), j);
            if (p > best) best = p;
        }
    }
    g_posidx[i] = (int)(0xFFFFFFFFu - (uint32_t)best);
}

// ---------------- finalize: per-anchor losses -------------------------------
__global__ void finalize_k(const float* __restrict__ emb,
                           const int* __restrict__ labels,
                           const float* __restrict__ beta) {
    int w = (blockIdx.x * blockDim.x + threadIdx.x) >> 5;
    int lane = threadIdx.x & 31;
    if (w >= NB) return;
    int pi = g_posidx[w], ni = g_negidx[w];
    float4 a = *(const float4*)(emb + w * NDIM + lane * 4);
    float4 p = *(const float4*)(emb + pi * NDIM + lane * 4);
    float4 n = *(const float4*)(emb + ni * NDIM + lane * 4);
    float dx, sap, san;
    dx = a.x - p.x; sap = dx * dx; dx = a.y - p.y; sap += dx * dx;
    dx = a.z - p.z; sap += dx * dx; dx = a.w - p.w; sap += dx * dx;
    dx = a.x - n.x; san = dx * dx; dx = a.y - n.y; san += dx * dx;
    dx = a.z - n.z; san += dx * dx; dx = a.w - n.w; san += dx * dx;
#pragma unroll
    for (int o = 16; o; o >>= 1) {
        sap += __shfl_xor_sync(0xFFFFFFFFu, sap, o);
        san += __shfl_xor_sync(0xFFFFFFFFu, san, o);
    }
    if (lane == 0) {
        float d_ap = sqrtf(sap + 1e-8f);
        float d_an = sqrtf(san + 1e-8f);
        float ba = beta[labels[w]];
        float pl = fmaxf(d_ap - ba + 0.2f, 0.0f);
        float nl = fmaxf(ba - d_an + 0.2f, 0.0f);
        g_loss[w] = pl + nl;
        g_cnt[w]  = (pl > 0.0f ? 1.0f : 0.0f) + (nl > 0.0f ? 1.0f : 0.0f);
    }
}

__global__ void reduce_k(float* __restrict__ out) {
    __shared__ float st[256], sc[256];
    int t = threadIdx.x;
    float s = 0.f, c = 0.f;
    for (int i = t; i < NB; i += 256) { s += g_loss[i]; c += g_cnt[i]; }
    st[t] = s; sc[t] = c;
    __syncthreads();
    for (int o = 128; o; o >>= 1) {
        if (t < o) { st[t] += st[t + o]; sc[t] += sc[t + o]; }
        __syncthreads();
    }
    if (t == 0) out[0] = (sc[0] == 0.0f) ? st[0] : st[0] / sc[0];
}

// ---------------- host -------------------------------------------------------
extern "C" void kernel_launch(void* const* d_in, const int* in_sizes, int n_in,
                              void* d_out, int out_size) {
    const float* emb    = (const float*)d_in[0];
    const int*   labels = (const int*)d_in[1];
    const float* beta   = (const float*)d_in[2];
    float* out = (float*)d_out;

    uint32_t kn0, kn1, kp0, kp1;
#if JAX_PARTITIONABLE
    tf2x32(0u, 42u, 0u, 0u, kn0, kn1);   // foldlike split: k_neg
    tf2x32(0u, 42u, 0u, 1u, kp0, kp1);   // k_pos
#else
    uint32_t a0, b0, a1, b1;
    tf2x32(0u, 42u, 0u, 2u, a0, b0);
    tf2x32(0u, 42u, 1u, 3u, a1, b1);
    kn0 = a0; kn1 = a1; kp0 = b0; kp1 = b1;
#endif

    const int smem = NDIM * BM * 4 + NDIM * BN * 4 + BN * 4 + BN * 4 + BM * 8;
    cudaFuncSetAttribute(neg_sample_k,
                         cudaFuncAttributeMaxDynamicSharedMemorySize, smem);

    transpose_k<<<dim3(NB / 32, NDIM / 32), dim3(32, 8)>>>(emb);
    norm_k<<<NB * 32 / 256, 256>>>(emb);
    neg_sample_k<<<NB / BM, NTHREADS, smem>>>(labels, kn0, kn1);
    pos_sample_k<<<NB / 128, 128>>>(labels, kp0, kp1);
    finalize_k<<<NB * 32 / 256, 256>>>(emb, labels, beta);
    reduce_k<<<1, 256>>>(out);
}

// round 5
// speedup vs baseline: 2.6445x; 2.6445x over previous
#include <cuda_runtime.h>
#include <cuda_bf16.h>
#include <cstdint>
#include <cfloat>

#define NB      4096
#define NDIM    128
#define BM      32
#define BN      128
#define NSPLIT  4
#define COLS_PER_SPLIT (NB / NSPLIT)
#define NTHREADS 256

// ---------------- device scratch (static, no allocation) --------------------
__device__ float g_embT[NDIM * NB];
__device__ float g_sqnorm[NB];
__device__ unsigned long long g_best[NB];   // packed (value,idx) argmax, neg
__device__ int   g_posidx[NB];
__device__ float g_loss[NB];
__device__ float g_cnt[NB];

// ---------------- threefry2x32 ----------------------------------------------
__host__ __device__ __forceinline__ void tf2x32(uint32_t k0, uint32_t k1,
                                                uint32_t c0, uint32_t c1,
                                                uint32_t& o0, uint32_t& o1) {
    const uint32_t ks2 = k0 ^ k1 ^ 0x1BD11BDAu;
    uint32_t x0 = c0 + k0;
    uint32_t x1 = c1 + k1;
#define TFR(r) { x0 += x1; x1 = (x1 << r) | (x1 >> (32 - r)); x1 ^= x0; }
    TFR(13) TFR(15) TFR(26) TFR(6)   x0 += k1;  x1 += ks2 + 1u;
    TFR(17) TFR(29) TFR(16) TFR(24)  x0 += ks2; x1 += k0  + 2u;
    TFR(13) TFR(15) TFR(26) TFR(6)   x0 += k0;  x1 += k1  + 3u;
    TFR(17) TFR(29) TFR(16) TFR(24)  x0 += k1;  x1 += ks2 + 4u;
    TFR(13) TFR(15) TFR(26) TFR(6)   x0 += ks2; x1 += k0  + 5u;
#undef TFR
    o0 = x0; o1 = x1;
}

// jax partitionable random bits for flat index n
__device__ __forceinline__ uint32_t jax_bits32(uint32_t k0, uint32_t k1, uint32_t n) {
    uint32_t o0, o1;
    tf2x32(k0, k1, 0u, n, o0, o1);
    return o0 ^ o1;
}

__device__ __forceinline__ float jax_gumbel(uint32_t bits) {
    float f = __uint_as_float((bits >> 9) | 0x3f800000u) - 1.0f;
    float u = fmaxf(f, 1.17549435e-38f);
    float nl = -logf(u);               // accurate: u->1 tail matters
    return -__logf(nl);
}

// pack (value, idx) so max() == argmax, first-index tie-break
__device__ __forceinline__ unsigned long long pack_vi(float v, int idx) {
    uint32_t s = __float_as_uint(v);
    s = (s & 0x80000000u) ? ~s : (s | 0x80000000u);
    return ((unsigned long long)s << 32) | (uint32_t)(0xFFFFFFFFu - (uint32_t)idx);
}

// ---------------- prep kernels ----------------------------------------------
__global__ void transpose_k(const float* __restrict__ emb) {
    __shared__ float t[32][33];
    int rb = blockIdx.x * 32, kb = blockIdx.y * 32;
    int tx = threadIdx.x, ty = threadIdx.y;
#pragma unroll
    for (int j = 0; j < 4; j++)
        t[ty + j * 8][tx] = emb[(rb + ty + j * 8) * NDIM + kb + tx];
    __syncthreads();
#pragma unroll
    for (int j = 0; j < 4; j++)
        g_embT[(kb + ty + j * 8) * NB + rb + tx] = t[tx][ty + j * 8];
}

__global__ void norm_k(const float* __restrict__ emb) {
    int w = (blockIdx.x * blockDim.x + threadIdx.x) >> 5;
    int lane = threadIdx.x & 31;
    if (w >= NB) return;
    float4 v = *(const float4*)(emb + w * NDIM + lane * 4);
    float s = v.x * v.x + v.y * v.y + v.z * v.z + v.w * v.w;
#pragma unroll
    for (int o = 16; o; o >>= 1) s += __shfl_xor_sync(0xFFFFFFFFu, s, o);
    if (lane == 0) { g_sqnorm[w] = s; g_best[w] = 0ull; }   // reset every launch
}

// ---------------- negatives: Gram tile + logits + gumbel + argmax -----------
__global__ void __launch_bounds__(NTHREADS, 2)
neg_sample_k(const int* __restrict__ labels, uint32_t kn0, uint32_t kn1) {
    extern __shared__ char sm[];
    float* A_s = (float*)sm;                       // [128][32]  k-major
    float* B_s = A_s + NDIM * BM;                  // [128][128] k-major
    int*   labc = (int*)(B_s + NDIM * BN);         // [128]
    float* sqc  = (float*)(labc + BN);             // [128]
    unsigned long long* red = (unsigned long long*)(sqc + BN);   // [32]

    const int tid = threadIdx.x;
    const int tr = tid >> 5;
    const int tc = tid & 31;
    const int row0 = blockIdx.x * BM;
    const int col0 = blockIdx.y * COLS_PER_SPLIT;

    float sqr[4]; int labr[4];
#pragma unroll
    for (int m = 0; m < 4; m++) {
        sqr[m]  = g_sqnorm[row0 + tr * 4 + m];
        labr[m] = labels[row0 + tr * 4 + m];
    }
    unsigned long long best[4] = {0ull, 0ull, 0ull, 0ull};

    for (int idx = tid; idx < NDIM * BM; idx += NTHREADS) {
        int k = idx >> 5, q = idx & 31;
        A_s[k * BM + q] = g_embT[k * NB + row0 + q];
    }

    for (int ct = col0; ct < col0 + COLS_PER_SPLIT; ct += BN) {
        __syncthreads();
        for (int idx = tid; idx < NDIM * BN / 4; idx += NTHREADS) {
            int k = idx >> 5, q = idx & 31;
            *(float4*)&B_s[k * BN + q * 4] =
                *(const float4*)&g_embT[k * NB + ct + q * 4];
        }
        if (tid < BN) { labc[tid] = labels[ct + tid]; sqc[tid] = g_sqnorm[ct + tid]; }
        __syncthreads();

        float acc[4][4];
#pragma unroll
        for (int m = 0; m < 4; m++)
#pragma unroll
            for (int c = 0; c < 4; c++) acc[m][c] = 0.f;

#pragma unroll 8
        for (int k = 0; k < NDIM; k++) {
            float4 a = *(const float4*)(A_s + k * BM + (tr << 2));
            float4 b = *(const float4*)(B_s + k * BN + (tc << 2));
            acc[0][0] = fmaf(a.x, b.x, acc[0][0]);
            acc[0][1] = fmaf(a.x, b.y, acc[0][1]);
            acc[0][2] = fmaf(a.x, b.z, acc[0][2]);
            acc[0][3] = fmaf(a.x, b.w, acc[0][3]);
            acc[1][0] = fmaf(a.y, b.x, acc[1][0]);
            acc[1][1] = fmaf(a.y, b.y, acc[1][1]);
            acc[1][2] = fmaf(a.y, b.z, acc[1][2]);
            acc[1][3] = fmaf(a.y, b.w, acc[1][3]);
            acc[2][0] = fmaf(a.z, b.x, acc[2][0]);
            acc[2][1] = fmaf(a.z, b.y, acc[2][1]);
            acc[2][2] = fmaf(a.z, b.z, acc[2][2]);
            acc[2][3] = fmaf(a.z, b.w, acc[2][3]);
            acc[3][0] = fmaf(a.w, b.x, acc[3][0]);
            acc[3][1] = fmaf(a.w, b.y, acc[3][1]);
            acc[3][2] = fmaf(a.w, b.z, acc[3][2]);
            acc[3][3] = fmaf(a.w, b.w, acc[3][3]);
        }

#pragma unroll
        for (int cc = 0; cc < 4; cc++) {
            const int jl = tc * 4 + cc;
            const int j  = ct + jl;
            const int labj = labc[jl];
            const float sqj = sqc[jl];
#pragma unroll
            for (int m = 0; m < 4; m++) {
                if (labr[m] == labj) continue;      // same-label -> -inf logit
                const int i = row0 + tr * 4 + m;
                float d2 = (sqr[m] + sqj) - 2.0f * acc[m][cc];
                d2 = fmaxf(d2, 0.25f);              // == clip d at 0.5
                float d = sqrtf(d2);
                float lq = -126.0f * __logf(d)
                           - 62.5f * log1pf((-0.25f * d) * d);
                uint32_t bits = jax_bits32(kn0, kn1, (uint32_t)(i * NB + j));
                float v = lq + jax_gumbel(bits);
                unsigned long long p = pack_vi(v, j);
                if (p > best[m]) best[m] = p;
            }
        }
    }

    __syncthreads();
    if (tid < BM) red[tid] = 0ull;
    __syncthreads();
#pragma unroll
    for (int m = 0; m < 4; m++)
        atomicMax(&red[tr * 4 + m], best[m]);
    __syncthreads();
    if (tid < BM)
        atomicMax(&g_best[row0 + tid], red[tid]);
}

// ---------------- positives: warp-per-anchor gumbel argmax ------------------
__global__ void pos_sample_k(const int* __restrict__ labels,
                             uint32_t kp0, uint32_t kp1) {
    __shared__ int lab[NB];
    const int t = threadIdx.x;
    for (int i = t; i < NB; i += 256) lab[i] = labels[i];
    __syncthreads();

    const int warp = (blockIdx.x * 256 + t) >> 5;   // anchor index
    const int lane = t & 31;
    const int li = lab[warp];
    unsigned long long best = 0ull;
    for (int j = lane; j < NB; j += 32) {
        if (lab[j] == li && j != warp) {
            uint32_t bits = jax_bits32(kp0, kp1, (uint32_t)(warp * NB + j));
            unsigned long long p = pack_vi(jax_gumbel(bits), j);
            if (p > best) best = p;
        }
    }
#pragma unroll
    for (int o = 16; o; o >>= 1) {
        unsigned long long q = __shfl_xor_sync(0xFFFFFFFFu, best, o);
        if (q > best) best = q;
    }
    if (lane == 0)
        g_posidx[warp] = (int)(0xFFFFFFFFu - (uint32_t)best);
}

// ---------------- finalize: per-anchor losses -------------------------------
__global__ void finalize_k(const float* __restrict__ emb,
                           const int* __restrict__ labels,
                           const float* __restrict__ beta) {
    int w = (blockIdx.x * blockDim.x + threadIdx.x) >> 5;
    int lane = threadIdx.x & 31;
    if (w >= NB) return;
    int pi = g_posidx[w];
    int ni = (int)(0xFFFFFFFFu - (uint32_t)g_best[w]);
    float4 a = *(const float4*)(emb + w * NDIM + lane * 4);
    float4 p = *(const float4*)(emb + pi * NDIM + lane * 4);
    float4 n = *(const float4*)(emb + ni * NDIM + lane * 4);
    float dx, sap, san;
    dx = a.x - p.x; sap = dx * dx; dx = a.y - p.y; sap += dx * dx;
    dx = a.z - p.z; sap += dx * dx; dx = a.w - p.w; sap += dx * dx;
    dx = a.x - n.x; san = dx * dx; dx = a.y - n.y; san += dx * dx;
    dx = a.z - n.z; san += dx * dx; dx = a.w - n.w; san += dx * dx;
#pragma unroll
    for (int o = 16; o; o >>= 1) {
        sap += __shfl_xor_sync(0xFFFFFFFFu, sap, o);
        san += __shfl_xor_sync(0xFFFFFFFFu, san, o);
    }
    if (lane == 0) {
        float d_ap = sqrtf(sap + 1e-8f);
        float d_an = sqrtf(san + 1e-8f);
        float ba = beta[labels[w]];
        float pl = fmaxf(d_ap - ba + 0.2f, 0.0f);
        float nl = fmaxf(ba - d_an + 0.2f, 0.0f);
        g_loss[w] = pl + nl;
        g_cnt[w]  = (pl > 0.0f ? 1.0f : 0.0f) + (nl > 0.0f ? 1.0f : 0.0f);
    }
}

__global__ void reduce_k(float* __restrict__ out) {
    __shared__ float st[256], sc[256];
    int t = threadIdx.x;
    float s = 0.f, c = 0.f;
    for (int i = t; i < NB; i += 256) { s += g_loss[i]; c += g_cnt[i]; }
    st[t] = s; sc[t] = c;
    __syncthreads();
    for (int o = 128; o; o >>= 1) {
        if (t < o) { st[t] += st[t + o]; sc[t] += sc[t + o]; }
        __syncthreads();
    }
    if (t == 0) out[0] = (sc[0] == 0.0f) ? st[0] : st[0] / sc[0];
}

// ---------------- host -------------------------------------------------------
extern "C" void kernel_launch(void* const* d_in, const int* in_sizes, int n_in,
                              void* d_out, int out_size) {
    const float* emb    = (const float*)d_in[0];
    const int*   labels = (const int*)d_in[1];
    const float* beta   = (const float*)d_in[2];
    float* out = (float*)d_out;

    uint32_t kn0, kn1, kp0, kp1;
    tf2x32(0u, 42u, 0u, 0u, kn0, kn1);   // foldlike split: k_neg
    tf2x32(0u, 42u, 0u, 1u, kp0, kp1);   // k_pos

    const int smem = NDIM * BM * 4 + NDIM * BN * 4 + BN * 4 + BN * 4 + BM * 8;
    cudaFuncSetAttribute(neg_sample_k,
                         cudaFuncAttributeMaxDynamicSharedMemorySize, smem);

    transpose_k<<<dim3(NB / 32, NDIM / 32), dim3(32, 8)>>>(emb);
    norm_k<<<NB * 32 / 256, 256>>>(emb);
    neg_sample_k<<<dim3(NB / BM, NSPLIT), NTHREADS, smem>>>(labels, kn0, kn1);
    pos_sample_k<<<NB / 8, 256>>>(labels, kp0, kp1);
    finalize_k<<<NB * 32 / 256, 256>>>(emb, labels, beta);
    reduce_k<<<1, 256>>>(out);
}

// round 6
// speedup vs baseline: 3.4311x; 1.2974x over previous
#include <cuda_runtime.h>
#include <cuda_bf16.h>
#include <cstdint>
#include <cfloat>

#define NB      4096
#define NDIM    128
#define BM      32
#define BN      128
#define NSPLIT  8
#define COLS_PER_SPLIT (NB / NSPLIT)
#define NTHREADS 256
#define NCLASS  100
#define MAXMEM  64

// ---------------- device scratch (static, no allocation) --------------------
__device__ float g_embT[NDIM * NB];
__device__ float g_sqnorm[NB];
__device__ unsigned long long g_best[NB];   // packed (value,idx) argmax, neg
__device__ int   g_posidx[NB];
__device__ float g_loss[NB];
__device__ float g_cnt[NB];
__device__ int   g_ccnt[NCLASS];
__device__ int   g_members[NCLASS * MAXMEM];

// ---------------- threefry2x32 ----------------------------------------------
__host__ __device__ __forceinline__ void tf2x32(uint32_t k0, uint32_t k1,
                                                uint32_t c0, uint32_t c1,
                                                uint32_t& o0, uint32_t& o1) {
    const uint32_t ks2 = k0 ^ k1 ^ 0x1BD11BDAu;
    uint32_t x0 = c0 + k0;
    uint32_t x1 = c1 + k1;
#define TFR(r) { x0 += x1; x1 = (x1 << r) | (x1 >> (32 - r)); x1 ^= x0; }
    TFR(13) TFR(15) TFR(26) TFR(6)   x0 += k1;  x1 += ks2 + 1u;
    TFR(17) TFR(29) TFR(16) TFR(24)  x0 += ks2; x1 += k0  + 2u;
    TFR(13) TFR(15) TFR(26) TFR(6)   x0 += k0;  x1 += k1  + 3u;
    TFR(17) TFR(29) TFR(16) TFR(24)  x0 += k1;  x1 += ks2 + 4u;
    TFR(13) TFR(15) TFR(26) TFR(6)   x0 += ks2; x1 += k0  + 5u;
#undef TFR
    o0 = x0; o1 = x1;
}

// jax partitionable random bits for flat index n
__device__ __forceinline__ uint32_t jax_bits32(uint32_t k0, uint32_t k1, uint32_t n) {
    uint32_t o0, o1;
    tf2x32(k0, k1, 0u, n, o0, o1);
    return o0 ^ o1;
}

__device__ __forceinline__ float jax_gumbel(uint32_t bits) {
    float f = __uint_as_float((bits >> 9) | 0x3f800000u) - 1.0f;
    float u = fmaxf(f, 1.17549435e-38f);
    float nl = -logf(u);               // accurate: u->1 tail decides winners
    return -__logf(nl);
}

// pack (value, idx) so max() == argmax, first-index tie-break
__device__ __forceinline__ unsigned long long pack_vi(float v, int idx) {
    uint32_t s = __float_as_uint(v);
    s = (s & 0x80000000u) ? ~s : (s | 0x80000000u);
    return ((unsigned long long)s << 32) | (uint32_t)(0xFFFFFFFFu - (uint32_t)idx);
}

// ---------------- prep kernels ----------------------------------------------
__global__ void transpose_k(const float* __restrict__ emb) {
    __shared__ float t[32][33];
    int rb = blockIdx.x * 32, kb = blockIdx.y * 32;
    int tx = threadIdx.x, ty = threadIdx.y;
#pragma unroll
    for (int j = 0; j < 4; j++)
        t[ty + j * 8][tx] = emb[(rb + ty + j * 8) * NDIM + kb + tx];
    __syncthreads();
#pragma unroll
    for (int j = 0; j < 4; j++)
        g_embT[(kb + ty + j * 8) * NB + rb + tx] = t[tx][ty + j * 8];
}

__global__ void norm_k(const float* __restrict__ emb) {
    int gid = blockIdx.x * blockDim.x + threadIdx.x;
    if (gid < NCLASS) g_ccnt[gid] = 0;          // reset class bins each launch
    int w = gid >> 5;
    int lane = threadIdx.x & 31;
    if (w >= NB) return;
    float4 v = *(const float4*)(emb + w * NDIM + lane * 4);
    float s = v.x * v.x + v.y * v.y + v.z * v.z + v.w * v.w;
#pragma unroll
    for (int o = 16; o; o >>= 1) s += __shfl_xor_sync(0xFFFFFFFFu, s, o);
    if (lane == 0) { g_sqnorm[w] = s; g_best[w] = 0ull; }   // reset every launch
}

__global__ void bin_k(const int* __restrict__ labels) {
    int i = blockIdx.x * blockDim.x + threadIdx.x;
    if (i >= NB) return;
    int c = labels[i];
    int s = atomicAdd(&g_ccnt[c], 1);
    if (s < MAXMEM) g_members[c * MAXMEM + s] = i;
}

// ---------------- negatives: Gram tile + logits + gumbel + argmax -----------
__global__ void __launch_bounds__(NTHREADS, 2)
neg_sample_k(const int* __restrict__ labels, uint32_t kn0, uint32_t kn1) {
    extern __shared__ char sm[];
    float* A_s = (float*)sm;                       // [128][32]  k-major
    float* B_s = A_s + NDIM * BM;                  // [128][128] k-major
    int*   labc = (int*)(B_s + NDIM * BN);         // [128]
    float* sqc  = (float*)(labc + BN);             // [128]
    unsigned long long* red = (unsigned long long*)(sqc + BN);   // [32]

    const int tid = threadIdx.x;
    const int tr = tid >> 5;
    const int tc = tid & 31;
    const int row0 = blockIdx.x * BM;
    const int col0 = blockIdx.y * COLS_PER_SPLIT;

    float sqr[4]; int labr[4];
#pragma unroll
    for (int m = 0; m < 4; m++) {
        sqr[m]  = g_sqnorm[row0 + tr * 4 + m];
        labr[m] = labels[row0 + tr * 4 + m];
    }
    unsigned long long best[4] = {0ull, 0ull, 0ull, 0ull};

    for (int idx = tid; idx < NDIM * BM; idx += NTHREADS) {
        int k = idx >> 5, q = idx & 31;
        A_s[k * BM + q] = g_embT[k * NB + row0 + q];
    }

    for (int ct = col0; ct < col0 + COLS_PER_SPLIT; ct += BN) {
        __syncthreads();
        for (int idx = tid; idx < NDIM * BN / 4; idx += NTHREADS) {
            int k = idx >> 5, q = idx & 31;
            *(float4*)&B_s[k * BN + q * 4] =
                *(const float4*)&g_embT[k * NB + ct + q * 4];
        }
        if (tid < BN) { labc[tid] = labels[ct + tid]; sqc[tid] = g_sqnorm[ct + tid]; }
        __syncthreads();

        float acc[4][4];
#pragma unroll
        for (int m = 0; m < 4; m++)
#pragma unroll
            for (int c = 0; c < 4; c++) acc[m][c] = 0.f;

#pragma unroll 8
        for (int k = 0; k < NDIM; k++) {
            float4 a = *(const float4*)(A_s + k * BM + (tr << 2));
            float4 b = *(const float4*)(B_s + k * BN + (tc << 2));
            acc[0][0] = fmaf(a.x, b.x, acc[0][0]);
            acc[0][1] = fmaf(a.x, b.y, acc[0][1]);
            acc[0][2] = fmaf(a.x, b.z, acc[0][2]);
            acc[0][3] = fmaf(a.x, b.w, acc[0][3]);
            acc[1][0] = fmaf(a.y, b.x, acc[1][0]);
            acc[1][1] = fmaf(a.y, b.y, acc[1][1]);
            acc[1][2] = fmaf(a.y, b.z, acc[1][2]);
            acc[1][3] = fmaf(a.y, b.w, acc[1][3]);
            acc[2][0] = fmaf(a.z, b.x, acc[2][0]);
            acc[2][1] = fmaf(a.z, b.y, acc[2][1]);
            acc[2][2] = fmaf(a.z, b.z, acc[2][2]);
            acc[2][3] = fmaf(a.z, b.w, acc[2][3]);
            acc[3][0] = fmaf(a.w, b.x, acc[3][0]);
            acc[3][1] = fmaf(a.w, b.y, acc[3][1]);
            acc[3][2] = fmaf(a.w, b.z, acc[3][2]);
            acc[3][3] = fmaf(a.w, b.w, acc[3][3]);
        }

#pragma unroll
        for (int cc = 0; cc < 4; cc++) {
            const int jl = tc * 4 + cc;
            const int j  = ct + jl;
            const int labj = labc[jl];
            const float sqj = sqc[jl];
#pragma unroll
            for (int m = 0; m < 4; m++) {
                if (labr[m] == labj) continue;      // same-label -> -inf logit
                const int i = row0 + tr * 4 + m;
                float d2 = (sqr[m] + sqj) - 2.0f * acc[m][cc];
                d2 = fmaxf(d2, 0.25f);              // == clip d at 0.5
                d2 = fminf(d2, 3.999f);             // guard log(<=0); never hit
                // lq = -126 ln d - 62.5 ln(1 - d^2/4)  (d = sqrt(d2))
                float lq = -63.0f * __logf(d2)
                           - 62.5f * __logf(fmaf(-0.25f, d2, 1.0f));
                uint32_t bits = jax_bits32(kn0, kn1, (uint32_t)(i * NB + j));
                float v = lq + jax_gumbel(bits);
                unsigned long long p = pack_vi(v, j);
                if (p > best[m]) best[m] = p;
            }
        }
    }

    __syncthreads();
    if (tid < BM) red[tid] = 0ull;
    __syncthreads();
#pragma unroll
    for (int m = 0; m < 4; m++)
        atomicMax(&red[tr * 4 + m], best[m]);
    __syncthreads();
    if (tid < BM)
        atomicMax(&g_best[row0 + tid], red[tid]);
}

// ---------------- positives: warp-per-anchor over class member list ---------
__global__ void pos_sample_k(const int* __restrict__ labels,
                             uint32_t kp0, uint32_t kp1) {
    const int t = threadIdx.x;
    const int anchor = (blockIdx.x * 256 + t) >> 5;
    const int lane = t & 31;
    const int li = labels[anchor];
    const int cnt = min(g_ccnt[li], MAXMEM);
    unsigned long long best = 0ull;
    for (int s = lane; s < cnt; s += 32) {
        int j = g_members[li * MAXMEM + s];
        if (j != anchor) {
            uint32_t bits = jax_bits32(kp0, kp1, (uint32_t)(anchor * NB + j));
            unsigned long long p = pack_vi(jax_gumbel(bits), j);
            if (p > best) best = p;
        }
    }
#pragma unroll
    for (int o = 16; o; o >>= 1) {
        unsigned long long q = __shfl_xor_sync(0xFFFFFFFFu, best, o);
        if (q > best) best = q;
    }
    if (lane == 0)
        g_posidx[anchor] = (int)(0xFFFFFFFFu - (uint32_t)best);
}

// ---------------- finalize: per-anchor losses -------------------------------
__global__ void finalize_k(const float* __restrict__ emb,
                           const int* __restrict__ labels,
                           const float* __restrict__ beta) {
    int w = (blockIdx.x * blockDim.x + threadIdx.x) >> 5;
    int lane = threadIdx.x & 31;
    if (w >= NB) return;
    int pi = g_posidx[w];
    int ni = (int)(0xFFFFFFFFu - (uint32_t)g_best[w]);
    float4 a = *(const float4*)(emb + w * NDIM + lane * 4);
    float4 p = *(const float4*)(emb + pi * NDIM + lane * 4);
    float4 n = *(const float4*)(emb + ni * NDIM + lane * 4);
    float dx, sap, san;
    dx = a.x - p.x; sap = dx * dx; dx = a.y - p.y; sap += dx * dx;
    dx = a.z - p.z; sap += dx * dx; dx = a.w - p.w; sap += dx * dx;
    dx = a.x - n.x; san = dx * dx; dx = a.y - n.y; san += dx * dx;
    dx = a.z - n.z; san += dx * dx; dx = a.w - n.w; san += dx * dx;
#pragma unroll
    for (int o = 16; o; o >>= 1) {
        sap += __shfl_xor_sync(0xFFFFFFFFu, sap, o);
        san += __shfl_xor_sync(0xFFFFFFFFu, san, o);
    }
    if (lane == 0) {
        float d_ap = sqrtf(sap + 1e-8f);
        float d_an = sqrtf(san + 1e-8f);
        float ba = beta[labels[w]];
        float pl = fmaxf(d_ap - ba + 0.2f, 0.0f);
        float nl = fmaxf(ba - d_an + 0.2f, 0.0f);
        g_loss[w] = pl + nl;
        g_cnt[w]  = (pl > 0.0f ? 1.0f : 0.0f) + (nl > 0.0f ? 1.0f : 0.0f);
    }
}

__global__ void reduce_k(float* __restrict__ out) {
    __shared__ float st[256], sc[256];
    int t = threadIdx.x;
    float s = 0.f, c = 0.f;
    for (int i = t; i < NB; i += 256) { s += g_loss[i]; c += g_cnt[i]; }
    st[t] = s; sc[t] = c;
    __syncthreads();
    for (int o = 128; o; o >>= 1) {
        if (t < o) { st[t] += st[t + o]; sc[t] += sc[t + o]; }
        __syncthreads();
    }
    if (t == 0) out[0] = (sc[0] == 0.0f) ? st[0] : st[0] / sc[0];
}

// ---------------- host -------------------------------------------------------
extern "C" void kernel_launch(void* const* d_in, const int* in_sizes, int n_in,
                              void* d_out, int out_size) {
    const float* emb    = (const float*)d_in[0];
    const int*   labels = (const int*)d_in[1];
    const float* beta   = (const float*)d_in[2];
    float* out = (float*)d_out;

    uint32_t kn0, kn1, kp0, kp1;
    tf2x32(0u, 42u, 0u, 0u, kn0, kn1);   // foldlike split: k_neg
    tf2x32(0u, 42u, 0u, 1u, kp0, kp1);   // k_pos

    const int smem = NDIM * BM * 4 + NDIM * BN * 4 + BN * 4 + BN * 4 + BM * 8;
    cudaFuncSetAttribute(neg_sample_k,
                         cudaFuncAttributeMaxDynamicSharedMemorySize, smem);

    transpose_k<<<dim3(NB / 32, NDIM / 32), dim3(32, 8)>>>(emb);
    norm_k<<<NB * 32 / 256, 256>>>(emb);
    bin_k<<<NB / 256, 256>>>(labels);
    neg_sample_k<<<dim3(NB / BM, NSPLIT), NTHREADS, smem>>>(labels, kn0, kn1);
    pos_sample_k<<<NB / 8, 256>>>(labels, kp0, kp1);
    finalize_k<<<NB * 32 / 256, 256>>>(emb, labels, beta);
    reduce_k<<<1, 256>>>(out);
}

// round 7
// speedup vs baseline: 5.0572x; 1.4739x over previous
#include <cuda_runtime.h>
#include <cuda_bf16.h>
#include <cstdint>
#include <cfloat>

#define NB      4096
#define NDIM    128
#define BT      64          // tile size (rows and cols)
#define NRT     (NB / BT)   // 64 row tiles
#define NPAIRS  (NRT * (NRT + 1) / 2)   // 2080 triangular tile pairs
#define NTHREADS 256
#define NCLASS  100
#define MAXMEM  64

// ---------------- device scratch (static, no allocation) --------------------
__device__ float g_embT[NDIM * NB];
__device__ float g_sqnorm[NB];
__device__ unsigned long long g_best[NB];   // packed (value,idx) argmax, neg
__device__ int   g_posidx[NB];
__device__ float g_loss[NB];
__device__ float g_cnt[NB];
__device__ int   g_ccnt[NCLASS];
__device__ int   g_members[NCLASS * MAXMEM];

// ---------------- threefry2x32 ----------------------------------------------
__host__ __device__ __forceinline__ void tf2x32(uint32_t k0, uint32_t k1,
                                                uint32_t c0, uint32_t c1,
                                                uint32_t& o0, uint32_t& o1) {
    const uint32_t ks2 = k0 ^ k1 ^ 0x1BD11BDAu;
    uint32_t x0 = c0 + k0;
    uint32_t x1 = c1 + k1;
#define TFR(r) { x0 += x1; x1 = (x1 << r) | (x1 >> (32 - r)); x1 ^= x0; }
    TFR(13) TFR(15) TFR(26) TFR(6)   x0 += k1;  x1 += ks2 + 1u;
    TFR(17) TFR(29) TFR(16) TFR(24)  x0 += ks2; x1 += k0  + 2u;
    TFR(13) TFR(15) TFR(26) TFR(6)   x0 += k0;  x1 += k1  + 3u;
    TFR(17) TFR(29) TFR(16) TFR(24)  x0 += k1;  x1 += ks2 + 4u;
    TFR(13) TFR(15) TFR(26) TFR(6)   x0 += ks2; x1 += k0  + 5u;
#undef TFR
    o0 = x0; o1 = x1;
}

__device__ __forceinline__ uint32_t jax_bits32(uint32_t k0, uint32_t k1, uint32_t n) {
    uint32_t o0, o1;
    tf2x32(k0, k1, 0u, n, o0, o1);
    return o0 ^ o1;
}

__device__ __forceinline__ float jax_gumbel(uint32_t bits) {
    float f = __uint_as_float((bits >> 9) | 0x3f800000u) - 1.0f;
    float u = fmaxf(f, 1.17549435e-38f);
    float nl = -logf(u);               // accurate: u->1 tail decides winners
    return -__logf(nl);
}

// pack (value, idx) so max() == argmax, first-index tie-break
__device__ __forceinline__ unsigned long long pack_vi(float v, int idx) {
    uint32_t s = __float_as_uint(v);
    s = (s & 0x80000000u) ? ~s : (s | 0x80000000u);
    return ((unsigned long long)s << 32) | (uint32_t)(0xFFFFFFFFu - (uint32_t)idx);
}

// ---------------- prep kernels ----------------------------------------------
__global__ void transpose_k(const float* __restrict__ emb) {
    __shared__ float t[32][33];
    int rb = blockIdx.x * 32, kb = blockIdx.y * 32;
    int tx = threadIdx.x, ty = threadIdx.y;
#pragma unroll
    for (int j = 0; j < 4; j++)
        t[ty + j * 8][tx] = emb[(rb + ty + j * 8) * NDIM + kb + tx];
    __syncthreads();
#pragma unroll
    for (int j = 0; j < 4; j++)
        g_embT[(kb + ty + j * 8) * NB + rb + tx] = t[tx][ty + j * 8];
}

__global__ void norm_k(const float* __restrict__ emb) {
    int gid = blockIdx.x * blockDim.x + threadIdx.x;
    if (gid < NCLASS) g_ccnt[gid] = 0;          // reset class bins each launch
    int w = gid >> 5;
    int lane = threadIdx.x & 31;
    if (w >= NB) return;
    float4 v = *(const float4*)(emb + w * NDIM + lane * 4);
    float s = v.x * v.x + v.y * v.y + v.z * v.z + v.w * v.w;
#pragma unroll
    for (int o = 16; o; o >>= 1) s += __shfl_xor_sync(0xFFFFFFFFu, s, o);
    if (lane == 0) { g_sqnorm[w] = s; g_best[w] = 0ull; }   // reset every launch
}

__global__ void bin_k(const int* __restrict__ labels) {
    int i = blockIdx.x * blockDim.x + threadIdx.x;
    if (i >= NB) return;
    int c = labels[i];
    int s = atomicAdd(&g_ccnt[c], 1);
    if (s < MAXMEM) g_members[c * MAXMEM + s] = i;
}

// ---------------- negatives: triangular tile pairs, dual-orientation --------
__global__ void __launch_bounds__(NTHREADS, 3)
neg_sample_k(const int* __restrict__ labels, uint32_t kn0, uint32_t kn1) {
    extern __shared__ char sm[];
    float* A_s = (float*)sm;                        // [128][64] k-major, tile I
    float* B_s = A_s + NDIM * BT;                   // [128][64] k-major, tile J
    int*   labA = (int*)(B_s + NDIM * BT);          // [64]
    int*   labB = labA + BT;                        // [64]
    float* sqA  = (float*)(labB + BT);              // [64]
    float* sqB  = sqA + BT;                         // [64]
    unsigned long long* redA = (unsigned long long*)(sqB + BT);  // [64]
    unsigned long long* redB = redA + BT;                        // [64]

    const int tid = threadIdx.x;
    const int tr = tid >> 4;          // 0..15 row group (4 rows)
    const int tc = tid & 15;          // 0..15 col group (4 cols)

    // decode triangular pair index: base(I) = I*(2*NRT+1-I)/2
    int bid = blockIdx.x;
    int I = (int)((2.0f * NRT + 1.0f
                   - sqrtf((2.0f * NRT + 1.0f) * (2.0f * NRT + 1.0f)
                           - 8.0f * (float)bid)) * 0.5f);
    while (I * (2 * NRT + 1 - I) / 2 > bid) I--;
    while ((I + 1) * (2 * NRT - I) / 2 <= bid) I++;
    const int J = I + (bid - I * (2 * NRT + 1 - I) / 2);
    const int row0 = I * BT;
    const int col0 = J * BT;
    const bool diag = (I == J);

    // load both tiles (k-major from embT)
    for (int idx = tid; idx < NDIM * BT / 4; idx += NTHREADS) {
        int k = idx >> 4, q = (idx & 15) << 2;
        *(float4*)&A_s[k * BT + q] = *(const float4*)&g_embT[k * NB + row0 + q];
        *(float4*)&B_s[k * BT + q] = *(const float4*)&g_embT[k * NB + col0 + q];
    }
    if (tid < BT) {
        labA[tid] = labels[row0 + tid]; sqA[tid] = g_sqnorm[row0 + tid];
        redA[tid] = 0ull; redB[tid] = 0ull;
    } else if (tid < 2 * BT) {
        int q = tid - BT;
        labB[q] = labels[col0 + q]; sqB[q] = g_sqnorm[col0 + q];
    }
    __syncthreads();

    float acc[4][4];
#pragma unroll
    for (int m = 0; m < 4; m++)
#pragma unroll
        for (int c = 0; c < 4; c++) acc[m][c] = 0.f;

#pragma unroll 4
    for (int k = 0; k < NDIM; k++) {
        float4 a = *(const float4*)(A_s + k * BT + (tr << 2));
        float4 b = *(const float4*)(B_s + k * BT + (tc << 2));
        acc[0][0] = fmaf(a.x, b.x, acc[0][0]);
        acc[0][1] = fmaf(a.x, b.y, acc[0][1]);
        acc[0][2] = fmaf(a.x, b.z, acc[0][2]);
        acc[0][3] = fmaf(a.x, b.w, acc[0][3]);
        acc[1][0] = fmaf(a.y, b.x, acc[1][0]);
        acc[1][1] = fmaf(a.y, b.y, acc[1][1]);
        acc[1][2] = fmaf(a.y, b.z, acc[1][2]);
        acc[1][3] = fmaf(a.y, b.w, acc[1][3]);
        acc[2][0] = fmaf(a.z, b.x, acc[2][0]);
        acc[2][1] = fmaf(a.z, b.y, acc[2][1]);
        acc[2][2] = fmaf(a.z, b.z, acc[2][2]);
        acc[2][3] = fmaf(a.z, b.w, acc[2][3]);
        acc[3][0] = fmaf(a.w, b.x, acc[3][0]);
        acc[3][1] = fmaf(a.w, b.y, acc[3][1]);
        acc[3][2] = fmaf(a.w, b.z, acc[3][2]);
        acc[3][3] = fmaf(a.w, b.w, acc[3][3]);
    }

    float sqr[4]; int labr[4];
#pragma unroll
    for (int m = 0; m < 4; m++) {
        sqr[m]  = sqA[tr * 4 + m];
        labr[m] = labA[tr * 4 + m];
    }

    unsigned long long best1[4] = {0ull, 0ull, 0ull, 0ull};  // per row (anchor i)
    unsigned long long best2[4] = {0ull, 0ull, 0ull, 0ull};  // per col (anchor j)

#pragma unroll
    for (int cc = 0; cc < 4; cc++) {
        const int jl = tc * 4 + cc;
        const int j  = col0 + jl;
        const int labj = labB[jl];
        const float sqj = sqB[jl];
#pragma unroll
        for (int m = 0; m < 4; m++) {
            if (labr[m] == labj) continue;          // same-label -> -inf logit
            const int i = row0 + tr * 4 + m;
            float d2 = (sqr[m] + sqj) - 2.0f * acc[m][cc];
            d2 = fmaxf(d2, 0.25f);                  // == clip d at 0.5
            d2 = fminf(d2, 3.999f);                 // guard log(<=0); never hit
            // lq = -126 ln d - 62.5 ln(1 - d^2/4)   (shared by both orientations)
            float lq = -63.0f * __logf(d2)
                       - 62.5f * __logf(fmaf(-0.25f, d2, 1.0f));
            // orientation 1: anchor i, candidate j
            {
                uint32_t bits = jax_bits32(kn0, kn1, (uint32_t)(i * NB + j));
                unsigned long long p = pack_vi(lq + jax_gumbel(bits), j);
                if (p > best1[m]) best1[m] = p;
            }
            // orientation 2: anchor j, candidate i (off-diagonal tiles only)
            if (!diag) {
                uint32_t bits = jax_bits32(kn0, kn1, (uint32_t)(j * NB + i));
                unsigned long long p = pack_vi(lq + jax_gumbel(bits), i);
                if (p > best2[cc]) best2[cc] = p;
            }
        }
    }

#pragma unroll
    for (int m = 0; m < 4; m++)
        if (best1[m]) atomicMax(&redA[tr * 4 + m], best1[m]);
    if (!diag) {
#pragma unroll
        for (int cc = 0; cc < 4; cc++)
            if (best2[cc]) atomicMax(&redB[tc * 4 + cc], best2[cc]);
    }
    __syncthreads();
    if (tid < BT) {
        if (redA[tid]) atomicMax(&g_best[row0 + tid], redA[tid]);
    } else if (tid < 2 * BT && !diag) {
        int q = tid - BT;
        if (redB[q]) atomicMax(&g_best[col0 + q], redB[q]);
    }
}

// ---------------- positives: warp-per-anchor over class member list ---------
__global__ void pos_sample_k(const int* __restrict__ labels,
                             uint32_t kp0, uint32_t kp1) {
    const int t = threadIdx.x;
    const int anchor = (blockIdx.x * 256 + t) >> 5;
    const int lane = t & 31;
    const int li = labels[anchor];
    const int cnt = min(g_ccnt[li], MAXMEM);
    unsigned long long best = 0ull;
    for (int s = lane; s < cnt; s += 32) {
        int j = g_members[li * MAXMEM + s];
        if (j != anchor) {
            uint32_t bits = jax_bits32(kp0, kp1, (uint32_t)(anchor * NB + j));
            unsigned long long p = pack_vi(jax_gumbel(bits), j);
            if (p > best) best = p;
        }
    }
#pragma unroll
    for (int o = 16; o; o >>= 1) {
        unsigned long long q = __shfl_xor_sync(0xFFFFFFFFu, best, o);
        if (q > best) best = q;
    }
    if (lane == 0)
        g_posidx[anchor] = (int)(0xFFFFFFFFu - (uint32_t)best);
}

// ---------------- finalize: per-anchor losses -------------------------------
__global__ void finalize_k(const float* __restrict__ emb,
                           const int* __restrict__ labels,
                           const float* __restrict__ beta) {
    int w = (blockIdx.x * blockDim.x + threadIdx.x) >> 5;
    int lane = threadIdx.x & 31;
    if (w >= NB) return;
    int pi = g_posidx[w];
    int ni = (int)(0xFFFFFFFFu - (uint32_t)g_best[w]);
    float4 a = *(const float4*)(emb + w * NDIM + lane * 4);
    float4 p = *(const float4*)(emb + pi * NDIM + lane * 4);
    float4 n = *(const float4*)(emb + ni * NDIM + lane * 4);
    float dx, sap, san;
    dx = a.x - p.x; sap = dx * dx; dx = a.y - p.y; sap += dx * dx;
    dx = a.z - p.z; sap += dx * dx; dx = a.w - p.w; sap += dx * dx;
    dx = a.x - n.x; san = dx * dx; dx = a.y - n.y; san += dx * dx;
    dx = a.z - n.z; san += dx * dx; dx = a.w - n.w; san += dx * dx;
#pragma unroll
    for (int o = 16; o; o >>= 1) {
        sap += __shfl_xor_sync(0xFFFFFFFFu, sap, o);
        san += __shfl_xor_sync(0xFFFFFFFFu, san, o);
    }
    if (lane == 0) {
        float d_ap = sqrtf(sap + 1e-8f);
        float d_an = sqrtf(san + 1e-8f);
        float ba = beta[labels[w]];
        float pl = fmaxf(d_ap - ba + 0.2f, 0.0f);
        float nl = fmaxf(ba - d_an + 0.2f, 0.0f);
        g_loss[w] = pl + nl;
        g_cnt[w]  = (pl > 0.0f ? 1.0f : 0.0f) + (nl > 0.0f ? 1.0f : 0.0f);
    }
}

__global__ void reduce_k(float* __restrict__ out) {
    __shared__ float st[256], sc[256];
    int t = threadIdx.x;
    float s = 0.f, c = 0.f;
    for (int i = t; i < NB; i += 256) { s += g_loss[i]; c += g_cnt[i]; }
    st[t] = s; sc[t] = c;
    __syncthreads();
    for (int o = 128; o; o >>= 1) {
        if (t < o) { st[t] += st[t + o]; sc[t] += sc[t + o]; }
        __syncthreads();
    }
    if (t == 0) out[0] = (sc[0] == 0.0f) ? st[0] : st[0] / sc[0];
}

// ---------------- host -------------------------------------------------------
extern "C" void kernel_launch(void* const* d_in, const int* in_sizes, int n_in,
                              void* d_out, int out_size) {
    const float* emb    = (const float*)d_in[0];
    const int*   labels = (const int*)d_in[1];
    const float* beta   = (const float*)d_in[2];
    float* out = (float*)d_out;

    uint32_t kn0, kn1, kp0, kp1;
    tf2x32(0u, 42u, 0u, 0u, kn0, kn1);   // foldlike split: k_neg
    tf2x32(0u, 42u, 0u, 1u, kp0, kp1);   // k_pos

    const int smem = 2 * (NDIM * BT * 4)        // A_s, B_s
                   + 2 * (BT * 4)               // labA, labB
                   + 2 * (BT * 4)               // sqA, sqB
                   + 2 * (BT * 8);              // redA, redB
    cudaFuncSetAttribute(neg_sample_k,
                         cudaFuncAttributeMaxDynamicSharedMemorySize, smem);

    transpose_k<<<dim3(NB / 32, NDIM / 32), dim3(32, 8)>>>(emb);
    norm_k<<<NB * 32 / 256, 256>>>(emb);
    bin_k<<<NB / 256, 256>>>(labels);
    neg_sample_k<<<NPAIRS, NTHREADS, smem>>>(labels, kn0, kn1);
    pos_sample_k<<<NB / 8, 256>>>(labels, kp0, kp1);
    finalize_k<<<NB * 32 / 256, 256>>>(emb, labels, beta);
    reduce_k<<<1, 256>>>(out);
}